// round 1
// baseline (speedup 1.0000x reference)
#include <cuda_runtime.h>
#include <cstddef>

// Dense FFN: out = relu(x @ w1 + b1) @ w2 + b2
// x: [8192, 1024] fp32, w1: [1024, 4096], b1: [4096], w2: [4096, 1024], b2: [1024]
// All row-major. Output: [8192, 1024] fp32.

#define M_TOTAL 8192
#define D_DIM   1024
#define W_DIM   4096

#define BM 128
#define BN 128
#define BK 16
#define TM 8
#define TN 8
// 256 threads: 16x16 grid, each thread computes 8x8 = four 4x4 quadrants
// rows {ty*4+ii, 64+ty*4+ii}, cols {tx*4+jj, 64+tx*4+jj}

// 128 MB scratch for the hidden activation [8192, 4096] fp32.
__device__ float g_hidden[(size_t)M_TOTAL * W_DIM];

template<bool RELU>
__global__ __launch_bounds__(256, 2)
void sgemm_bias_kernel(const float* __restrict__ A,   // [M, K]
                       const float* __restrict__ B,   // [K, N]
                       const float* __restrict__ bias,// [N]
                       float* __restrict__ C,         // [M, N]
                       int M, int N, int K)
{
    __shared__ float As[BK][BM];     // A transposed tile: As[k][m]
    __shared__ float Bs[BK][BN];     // B tile: Bs[k][n]

    const int tid = threadIdx.x;
    const int tx = tid & 15;         // 0..15
    const int ty = tid >> 4;         // 0..15
    const int bm = blockIdx.y * BM;
    const int bn = blockIdx.x * BN;

    // Global load mapping:
    // A: 128 rows x 16 cols = 2048 floats; each thread does 2x float4 (64 rows/pass)
    const int a_r = tid >> 2;              // 0..63
    const int a_c = (tid & 3) << 2;        // 0,4,8,12
    // B: 16 rows x 128 cols; each thread does 2x float4 (8 rows/pass)
    const int b_r = tid >> 5;              // 0..7
    const int b_c = (tid & 31) << 2;       // 0..124

    const float* Aptr = A + (size_t)bm * K;
    const float* Bptr = B + bn;

    float acc[TM][TN];
    #pragma unroll
    for (int i = 0; i < TM; i++)
        #pragma unroll
        for (int j = 0; j < TN; j++)
            acc[i][j] = 0.0f;

    for (int k0 = 0; k0 < K; k0 += BK) {
        // --- load A tile (transposed into smem) ---
        #pragma unroll
        for (int p = 0; p < 2; p++) {
            int r = a_r + p * 64;
            float4 v = *(const float4*)(Aptr + (size_t)r * K + (k0 + a_c));
            As[a_c + 0][r] = v.x;
            As[a_c + 1][r] = v.y;
            As[a_c + 2][r] = v.z;
            As[a_c + 3][r] = v.w;
        }
        // --- load B tile ---
        #pragma unroll
        for (int p = 0; p < 2; p++) {
            int r = b_r + p * 8;
            *(float4*)&Bs[r][b_c] =
                *(const float4*)(Bptr + (size_t)(k0 + r) * N + b_c);
        }
        __syncthreads();

        // --- compute ---
        #pragma unroll
        for (int k = 0; k < BK; k++) {
            float ra[TM], rb[TN];
            // two 4-wide fragments per dim, spaced 64 apart (conflict-reduced)
            *(float4*)&ra[0] = *(const float4*)&As[k][ty * 4];
            *(float4*)&ra[4] = *(const float4*)&As[k][64 + ty * 4];
            *(float4*)&rb[0] = *(const float4*)&Bs[k][tx * 4];
            *(float4*)&rb[4] = *(const float4*)&Bs[k][64 + tx * 4];
            #pragma unroll
            for (int i = 0; i < TM; i++)
                #pragma unroll
                for (int j = 0; j < TN; j++)
                    acc[i][j] += ra[i] * rb[j];
        }
        __syncthreads();
    }

    // --- epilogue: bias (+ relu), vectorized stores ---
    #pragma unroll
    for (int im = 0; im < 2; im++) {
        #pragma unroll
        for (int ii = 0; ii < 4; ii++) {
            int row = bm + im * 64 + ty * 4 + ii;
            int i = im * 4 + ii;
            #pragma unroll
            for (int jm = 0; jm < 2; jm++) {
                int col = bn + jm * 64 + tx * 4;
                float4 v;
                v.x = acc[i][jm * 4 + 0] + bias[col + 0];
                v.y = acc[i][jm * 4 + 1] + bias[col + 1];
                v.z = acc[i][jm * 4 + 2] + bias[col + 2];
                v.w = acc[i][jm * 4 + 3] + bias[col + 3];
                if (RELU) {
                    v.x = fmaxf(v.x, 0.0f);
                    v.y = fmaxf(v.y, 0.0f);
                    v.z = fmaxf(v.z, 0.0f);
                    v.w = fmaxf(v.w, 0.0f);
                }
                *(float4*)&C[(size_t)row * N + col] = v;
            }
        }
    }
}

extern "C" void kernel_launch(void* const* d_in, const int* in_sizes, int n_in,
                              void* d_out, int out_size)
{
    const float* x  = (const float*)d_in[0];   // [8192, 1024]
    const float* w1 = (const float*)d_in[1];   // [1024, 4096]
    const float* b1 = (const float*)d_in[2];   // [4096]
    const float* w2 = (const float*)d_in[3];   // [4096, 1024]
    const float* b2 = (const float*)d_in[4];   // [1024]
    float* out = (float*)d_out;                // [8192, 1024]

    float* h = nullptr;
    cudaGetSymbolAddress((void**)&h, g_hidden);

    dim3 blk(256);
    // GEMM1: h = relu(x @ w1 + b1)   [8192, 4096]
    dim3 g1(W_DIM / BN, M_TOTAL / BM);   // (32, 64)
    sgemm_bias_kernel<true><<<g1, blk>>>(x, w1, b1, h, M_TOTAL, W_DIM, D_DIM);

    // GEMM2: out = h @ w2 + b2       [8192, 1024]
    dim3 g2(D_DIM / BN, M_TOTAL / BM);   // (8, 64)
    sgemm_bias_kernel<false><<<g2, blk>>>(h, w2, b2, out, M_TOTAL, D_DIM, W_DIM);
}

// round 4
// speedup vs baseline: 3.1164x; 3.1164x over previous
#include <cuda_runtime.h>
#include <cuda_bf16.h>
#include <cstdint>
#include <cstddef>

// FFN: out = relu(x @ w1 + b1) @ w2 + b2
// bf16x3 split precision via mma.sync.m16n8k16 (sm_80+ PTX, works on plain sm_103 target).

#define M_TOTAL 8192
#define D_DIM   1024
#define W_DIM   4096

// ---- device scratch ----
__device__ __nv_bfloat16 g_xh[(size_t)M_TOTAL * D_DIM];
__device__ __nv_bfloat16 g_xl[(size_t)M_TOTAL * D_DIM];
__device__ __nv_bfloat16 g_hh[(size_t)M_TOTAL * W_DIM];
__device__ __nv_bfloat16 g_hl[(size_t)M_TOTAL * W_DIM];
__device__ __nv_bfloat16 g_w1th[(size_t)W_DIM * D_DIM];
__device__ __nv_bfloat16 g_w1tl[(size_t)W_DIM * D_DIM];
__device__ __nv_bfloat16 g_w2th[(size_t)D_DIM * W_DIM];
__device__ __nv_bfloat16 g_w2tl[(size_t)D_DIM * W_DIM];

// ---- helpers ----
__device__ __forceinline__ uint32_t smem_u32(const void* p) {
    uint32_t a;
    asm("{ .reg .u64 t; cvta.to.shared.u64 t, %1; cvt.u32.u64 %0, t; }" : "=r"(a) : "l"(p));
    return a;
}
__device__ __forceinline__ void cpasync16(uint32_t dst, const void* src) {
    asm volatile("cp.async.cg.shared.global [%0], [%1], 16;" :: "r"(dst), "l"(src));
}
__device__ __forceinline__ void cp_commit() {
    asm volatile("cp.async.commit_group;" ::: "memory");
}
__device__ __forceinline__ void cp_wait1() {
    asm volatile("cp.async.wait_group 1;" ::: "memory");
}
__device__ __forceinline__ void ldsm4(uint32_t* r, uint32_t addr) {
    asm volatile("ldmatrix.sync.aligned.m8n8.x4.shared.b16 {%0,%1,%2,%3}, [%4];"
                 : "=r"(r[0]), "=r"(r[1]), "=r"(r[2]), "=r"(r[3]) : "r"(addr));
}
__device__ __forceinline__ void mma16816(float* c, const uint32_t* a, uint32_t b0, uint32_t b1) {
    asm volatile("mma.sync.aligned.m16n8k16.row.col.f32.bf16.bf16.f32 "
                 "{%0,%1,%2,%3}, {%4,%5,%6,%7}, {%8,%9}, {%0,%1,%2,%3};"
                 : "+f"(c[0]), "+f"(c[1]), "+f"(c[2]), "+f"(c[3])
                 : "r"(a[0]), "r"(a[1]), "r"(a[2]), "r"(a[3]), "r"(b0), "r"(b1));
}
__device__ __forceinline__ void split_bf16(float v, __nv_bfloat16& hi, __nv_bfloat16& lo) {
    hi = __float2bfloat16_rn(v);
    lo = __float2bfloat16_rn(v - __bfloat162float(hi));
}

// ---- prepass: split fp32 -> bf16 hi/lo (elementwise) ----
__global__ void split_kernel(const float* __restrict__ X,
                             __nv_bfloat16* __restrict__ Xh,
                             __nv_bfloat16* __restrict__ Xl, size_t n4) {
    size_t i = (size_t)blockIdx.x * blockDim.x + threadIdx.x;
    if (i >= n4) return;
    float4 v = ((const float4*)X)[i];
    __nv_bfloat16 h0, h1, h2, h3, l0, l1, l2, l3;
    split_bf16(v.x, h0, l0); split_bf16(v.y, h1, l1);
    split_bf16(v.z, h2, l2); split_bf16(v.w, h3, l3);
    uint32_t ph0 = ((uint32_t)__bfloat16_as_ushort(h1) << 16) | __bfloat16_as_ushort(h0);
    uint32_t ph1 = ((uint32_t)__bfloat16_as_ushort(h3) << 16) | __bfloat16_as_ushort(h2);
    uint32_t pl0 = ((uint32_t)__bfloat16_as_ushort(l1) << 16) | __bfloat16_as_ushort(l0);
    uint32_t pl1 = ((uint32_t)__bfloat16_as_ushort(l3) << 16) | __bfloat16_as_ushort(l2);
    ((uint2*)Xh)[i] = make_uint2(ph0, ph1);
    ((uint2*)Xl)[i] = make_uint2(pl0, pl1);
}

// ---- prepass: W [K,N] fp32 -> W^T [N,K] bf16 hi/lo ----
__global__ void transpose_split_kernel(const float* __restrict__ W,
                                       __nv_bfloat16* __restrict__ Thi,
                                       __nv_bfloat16* __restrict__ Tlo,
                                       int K, int N) {
    __shared__ float t[32][33];
    int n0 = blockIdx.x * 32, k0 = blockIdx.y * 32;
    int tx = threadIdx.x, ty = threadIdx.y;
    #pragma unroll
    for (int j = 0; j < 4; j++)
        t[ty + 8 * j][tx] = W[(size_t)(k0 + ty + 8 * j) * N + n0 + tx];
    __syncthreads();
    #pragma unroll
    for (int j = 0; j < 4; j++) {
        float v = t[tx][ty + 8 * j];
        __nv_bfloat16 hi, lo;
        split_bf16(v, hi, lo);
        size_t o = (size_t)(n0 + ty + 8 * j) * K + k0 + tx;
        Thi[o] = hi;
        Tlo[o] = lo;
    }
}

// ---- main GEMM ----
// C[M,N] = (Ah+Al)[M,K] @ (Bh+Bl)^T, B given as [N,K].
// Tile 128x128x32, 3-stage cp.async, 8 warps (4x2), warp tile 32x64.
#define BMT 128
#define BNT 128
#define BKT 32
#define STAGES 3
#define ROWB 80                    // 32 bf16 = 64B + 16B pad
#define TILE_B (128 * ROWB)        // 10240
#define STAGE_B (4 * TILE_B)       // 40960
#define OFF_AH 0
#define OFF_AL TILE_B
#define OFF_BH (2 * TILE_B)
#define OFF_BL (3 * TILE_B)
#define SMEM_DYN (STAGES * STAGE_B)

template<bool SPLIT_OUT>
__global__ __launch_bounds__(256, 1)
void ffn_mma(const __nv_bfloat16* __restrict__ Ah, const __nv_bfloat16* __restrict__ Al,
             const __nv_bfloat16* __restrict__ Bh, const __nv_bfloat16* __restrict__ Bl,
             const float* __restrict__ bias,
             float* __restrict__ Cf,
             __nv_bfloat16* __restrict__ Chi, __nv_bfloat16* __restrict__ Clo,
             int M, int N, int K) {
    extern __shared__ char smem[];
    const uint32_t sbase = smem_u32(smem);
    const int tid = threadIdx.x;
    const int lane = tid & 31, wid = tid >> 5;
    const int wm = (wid >> 1) * 32, wn = (wid & 1) * 64;
    const int bm = blockIdx.y * BMT, bn = blockIdx.x * BNT;

    const __nv_bfloat16* Ahb = Ah + (size_t)bm * K;
    const __nv_bfloat16* Alb = Al + (size_t)bm * K;
    const __nv_bfloat16* Bhb = Bh + (size_t)bn * K;
    const __nv_bfloat16* Blb = Bl + (size_t)bn * K;

    const int ldr = tid >> 2;        // 0..63
    const int ldc = tid & 3;         // 16B chunk 0..3

    const int nIters = K / BKT;

    auto issue_stage = [&](int s) {
        uint32_t dst = sbase + (uint32_t)(s % STAGES) * STAGE_B;
        int k0 = s * BKT;
        #pragma unroll
        for (int h = 0; h < 2; h++) {
            int row = ldr + h * 64;
            uint32_t d = dst + (uint32_t)row * ROWB + (uint32_t)ldc * 16;
            size_t so = (size_t)row * K + k0 + ldc * 8;
            cpasync16(d + OFF_AH, Ahb + so);
            cpasync16(d + OFF_AL, Alb + so);
            cpasync16(d + OFF_BH, Bhb + so);
            cpasync16(d + OFF_BL, Blb + so);
        }
        cp_commit();
    };

    issue_stage(0);
    issue_stage(1);

    float acc[2][8][4];
    #pragma unroll
    for (int mi = 0; mi < 2; mi++)
        #pragma unroll
        for (int f = 0; f < 8; f++)
            #pragma unroll
            for (int q = 0; q < 4; q++)
                acc[mi][f][q] = 0.0f;

    const uint32_t arow = (uint32_t)(lane & 15) * ROWB + (uint32_t)(lane >> 4) * 16;

    for (int i = 0; i < nIters; i++) {
        cp_wait1();
        __syncthreads();
        if (i + 2 < nIters) issue_stage(i + 2);
        else cp_commit();   // keep group accounting so wait_group 1 is exact

        uint32_t sa = sbase + (uint32_t)(i % STAGES) * STAGE_B;

        #pragma unroll
        for (int kk = 0; kk < 2; kk++) {
            uint32_t ah[2][4], al[2][4], bh[4][4], bl[4][4];
            uint32_t koff = (uint32_t)(kk * 2) * 16;
            #pragma unroll
            for (int mi = 0; mi < 2; mi++) {
                uint32_t a = sa + (uint32_t)(wm + mi * 16) * ROWB + arow + koff;
                ldsm4(ah[mi], a + OFF_AH);
                ldsm4(al[mi], a + OFF_AL);
            }
            #pragma unroll
            for (int nb = 0; nb < 4; nb++) {
                uint32_t a = sa + (uint32_t)(wn + nb * 16) * ROWB + arow + koff;
                ldsm4(bh[nb], a + OFF_BH);
                ldsm4(bl[nb], a + OFF_BL);
            }
            #pragma unroll
            for (int mi = 0; mi < 2; mi++)
                #pragma unroll
                for (int f = 0; f < 8; f++) {
                    int nb = f >> 1, p = f & 1;
                    mma16816(acc[mi][f], ah[mi], bh[nb][p], bh[nb][2 + p]);
                    mma16816(acc[mi][f], al[mi], bh[nb][p], bh[nb][2 + p]);
                    mma16816(acc[mi][f], ah[mi], bl[nb][p], bl[nb][2 + p]);
                }
        }
        __syncthreads();
    }

    // ---- epilogue ----
    const int g = lane >> 2, t = lane & 3;
    #pragma unroll
    for (int mi = 0; mi < 2; mi++) {
        #pragma unroll
        for (int f = 0; f < 8; f++) {
            int row = bm + wm + mi * 16 + g;
            int col = bn + wn + f * 8 + t * 2;
            float b0 = __ldg(bias + col), b1 = __ldg(bias + col + 1);
            float v0 = acc[mi][f][0] + b0, v1 = acc[mi][f][1] + b1;
            float v2 = acc[mi][f][2] + b0, v3 = acc[mi][f][3] + b1;
            if (SPLIT_OUT) {
                v0 = fmaxf(v0, 0.f); v1 = fmaxf(v1, 0.f);
                v2 = fmaxf(v2, 0.f); v3 = fmaxf(v3, 0.f);
                __nv_bfloat16 h0, h1, h2, h3, l0, l1, l2, l3;
                split_bf16(v0, h0, l0); split_bf16(v1, h1, l1);
                split_bf16(v2, h2, l2); split_bf16(v3, h3, l3);
                uint32_t pa = ((uint32_t)__bfloat16_as_ushort(h1) << 16) | __bfloat16_as_ushort(h0);
                uint32_t pb = ((uint32_t)__bfloat16_as_ushort(h3) << 16) | __bfloat16_as_ushort(h2);
                uint32_t qa = ((uint32_t)__bfloat16_as_ushort(l1) << 16) | __bfloat16_as_ushort(l0);
                uint32_t qb = ((uint32_t)__bfloat16_as_ushort(l3) << 16) | __bfloat16_as_ushort(l2);
                *(uint32_t*)(Chi + (size_t)row * N + col) = pa;
                *(uint32_t*)(Chi + (size_t)(row + 8) * N + col) = pb;
                *(uint32_t*)(Clo + (size_t)row * N + col) = qa;
                *(uint32_t*)(Clo + (size_t)(row + 8) * N + col) = qb;
            } else {
                *(float2*)(Cf + (size_t)row * N + col) = make_float2(v0, v1);
                *(float2*)(Cf + (size_t)(row + 8) * N + col) = make_float2(v2, v3);
            }
        }
    }
}

extern "C" void kernel_launch(void* const* d_in, const int* in_sizes, int n_in,
                              void* d_out, int out_size) {
    const float* x  = (const float*)d_in[0];
    const float* w1 = (const float*)d_in[1];
    const float* b1 = (const float*)d_in[2];
    const float* w2 = (const float*)d_in[3];
    const float* b2 = (const float*)d_in[4];
    float* out = (float*)d_out;

    __nv_bfloat16 *xh, *xl, *hh, *hl, *w1th, *w1tl, *w2th, *w2tl;
    cudaGetSymbolAddress((void**)&xh, g_xh);
    cudaGetSymbolAddress((void**)&xl, g_xl);
    cudaGetSymbolAddress((void**)&hh, g_hh);
    cudaGetSymbolAddress((void**)&hl, g_hl);
    cudaGetSymbolAddress((void**)&w1th, g_w1th);
    cudaGetSymbolAddress((void**)&w1tl, g_w1tl);
    cudaGetSymbolAddress((void**)&w2th, g_w2th);
    cudaGetSymbolAddress((void**)&w2tl, g_w2tl);

    cudaFuncSetAttribute(ffn_mma<true>,  cudaFuncAttributeMaxDynamicSharedMemorySize, SMEM_DYN);
    cudaFuncSetAttribute(ffn_mma<false>, cudaFuncAttributeMaxDynamicSharedMemorySize, SMEM_DYN);

    // prepasses
    {
        size_t n4 = (size_t)M_TOTAL * D_DIM / 4;
        split_kernel<<<(unsigned)((n4 + 255) / 256), 256>>>(x, xh, xl, n4);
    }
    transpose_split_kernel<<<dim3(W_DIM / 32, D_DIM / 32), dim3(32, 8)>>>(w1, w1th, w1tl, D_DIM, W_DIM);
    transpose_split_kernel<<<dim3(D_DIM / 32, W_DIM / 32), dim3(32, 8)>>>(w2, w2th, w2tl, W_DIM, D_DIM);

    // GEMM1: h = relu(x @ w1 + b1), written as bf16 hi/lo
    ffn_mma<true><<<dim3(W_DIM / BNT, M_TOTAL / BMT), 256, SMEM_DYN>>>(
        xh, xl, w1th, w1tl, b1, nullptr, hh, hl, M_TOTAL, W_DIM, D_DIM);

    // GEMM2: out = h @ w2 + b2 (fp32 out)
    ffn_mma<false><<<dim3(D_DIM / BNT, M_TOTAL / BMT), 256, SMEM_DYN>>>(
        hh, hl, w2th, w2tl, b2, out, nullptr, nullptr, M_TOTAL, D_DIM, W_DIM);
}